// round 1
// baseline (speedup 1.0000x reference)
#include <cuda_runtime.h>
#include <cstdint>

#define IN 8192
#define OUT 8192
#define RWORDS (IN / 8)        // 1024 packed int32 rows
#define TPB 512                // 32 outputs x 16 K-slices
#define YDIM 16
#define OPB 32
#define KC (RWORDS / YDIM)     // 64 words per K-slice

// Exponent-OR dequant:
//   s & 0x00078000 places a nibble at mantissa bits [15:18] -> float = 1 + v/256
//   s & 0x00780000 places a nibble at mantissa bits [19:22] -> float = 1 + v/16
// With x' = x*256 (even k) or x*16 (odd k):
//   fma(x', t) = x' + x*v  ->  dot = sum(fma) - sum(x')
__global__ __launch_bounds__(TPB, 1)
void qmv_kernel(const float* __restrict__ x, const int* __restrict__ qw,
                const float* __restrict__ scales, const float* __restrict__ zeros,
                const float* __restrict__ bias, float* __restrict__ out) {
    __shared__ float4 xs4[IN / 4];     // pre-scaled x' (32 KB)
    __shared__ float red[TPB];         // per-(ky,ox) partial dots
    __shared__ float rs[YDIM], rsp[YDIM];  // per-warp plain / primed x sums

    const int tid  = threadIdx.x;
    const int lane = tid & 31;
    const int wid  = tid >> 5;   // == ky (blockDim = 32 x 16 flattened)
    const int ox   = lane;
    const int ky   = wid;

    // ---- stage x' into smem, accumulate plain and primed sums ----
    float sp = 0.f, spp = 0.f;
    const float4* xg = reinterpret_cast<const float4*>(x);
    for (int i = tid; i < IN / 4; i += TPB) {
        float4 v = xg[i];
        sp += (v.x + v.y) + (v.z + v.w);
        float4 vp = make_float4(v.x * 256.f, v.y * 16.f, v.z * 256.f, v.w * 16.f);
        spp += (vp.x + vp.y) + (vp.z + vp.w);
        xs4[i] = vp;
    }
    #pragma unroll
    for (int o = 16; o > 0; o >>= 1) {
        sp  += __shfl_down_sync(0xffffffffu, sp, o);
        spp += __shfl_down_sync(0xffffffffu, spp, o);
    }
    if (lane == 0) { rs[wid] = sp; rsp[wid] = spp; }
    __syncthreads();

    // ---- main loop: this thread handles output o over K-slice [r0, r0+KC) ----
    const int o  = blockIdx.x * OPB + ox;
    const int r0 = ky * KC;
    const unsigned* qp = reinterpret_cast<const unsigned*>(qw) + (size_t)r0 * OUT + o;

    float a0 = 0.f, a1 = 0.f, a2 = 0.f, a3 = 0.f;
    float a4 = 0.f, a5 = 0.f, a6 = 0.f, a7 = 0.f;
    const unsigned MLO = 0x00078000u, MHI = 0x00780000u, EXP = 0x3F800000u;

    #pragma unroll 4
    for (int r = 0; r < KC; r++) {
        unsigned w = qp[(size_t)r * OUT];
        float4 xa = xs4[(r0 + r) * 2];
        float4 xb = xs4[(r0 + r) * 2 + 1];
        unsigned s;
        s = w << 15;   // nibbles 0 -> [15:18], 1 -> [19:22]
        a0 = fmaf(xa.x, __uint_as_float(EXP | (s & MLO)), a0);
        a1 = fmaf(xa.y, __uint_as_float(EXP | (s & MHI)), a1);
        s = w << 7;    // nibbles 2, 3
        a2 = fmaf(xa.z, __uint_as_float(EXP | (s & MLO)), a2);
        a3 = fmaf(xa.w, __uint_as_float(EXP | (s & MHI)), a3);
        s = w >> 1;    // nibbles 4, 5
        a4 = fmaf(xb.x, __uint_as_float(EXP | (s & MLO)), a4);
        a5 = fmaf(xb.y, __uint_as_float(EXP | (s & MHI)), a5);
        s = w >> 9;    // nibbles 6, 7
        a6 = fmaf(xb.z, __uint_as_float(EXP | (s & MLO)), a6);
        a7 = fmaf(xb.w, __uint_as_float(EXP | (s & MHI)), a7);
    }
    red[tid] = ((a0 + a1) + (a2 + a3)) + ((a4 + a5) + (a6 + a7));
    __syncthreads();

    // ---- finish: reduce over K-slices, apply scales/zeros/bias ----
    if (tid < OPB) {
        float dot = 0.f;
        #pragma unroll
        for (int y = 0; y < YDIM; y++) dot += red[y * OPB + tid];
        float xsum = 0.f, xsumP = 0.f;
        #pragma unroll
        for (int i = 0; i < YDIM; i++) { xsum += rs[i]; xsumP += rsp[i]; }
        dot -= xsumP;  // remove the implicit-1.0 bias
        int oo = blockIdx.x * OPB + tid;
        out[oo] = bias[oo] + scales[oo] * dot - zeros[oo] * xsum;
    }
}

extern "C" void kernel_launch(void* const* d_in, const int* in_sizes, int n_in,
                              void* d_out, int out_size) {
    const float* x      = (const float*)d_in[0];
    const int*   qw     = (const int*)d_in[1];
    const float* scales = (const float*)d_in[2];
    const float* zeros  = (const float*)d_in[3];
    const float* bias   = (const float*)d_in[4];
    float* out = (float*)d_out;

    dim3 grid(OUT / OPB);   // 256 blocks
    dim3 block(TPB);        // 512 threads
    qmv_kernel<<<grid, block>>>(x, qw, scales, zeros, bias, out);
}

// round 2
// speedup vs baseline: 1.2737x; 1.2737x over previous
#include <cuda_runtime.h>
#include <cstdint>

#define IN 8192
#define OUT 8192
#define RW 1024            // packed int32 rows (IN/8)
#define TPB 512            // 8 output-quads x 4 rowgroups per warp, 16 warps
#define OPB 32             // outputs per block (8 quads)
#define NRG 64             // concurrent row-groups (16 warps x 4)
#define NIT (RW / NRG)     // 16 iterations per thread

// Exponent-OR dequant into a packed f32x2:
//   lo: EXP | (s & 0x00078000) = 1 + v_even/256   (pairs with x' = x*256)
//   hi: EXP | (s & 0x00780000) = 1 + v_odd /16    (pairs with x' = x*16)
//   fma.rn.f32x2(acc, xp, v) accumulates x'*1 + x*v; the Sum(x') bias is
//   subtracted once at the end.
__device__ __forceinline__ void dq_fma2(unsigned long long& acc, unsigned s,
                                        unsigned long long xp) {
    asm("{\n\t"
        ".reg .b32 lo, hi;\n\t"
        ".reg .b64 v;\n\t"
        "lop3.b32 lo, %1, 0x00078000, 0x3F800000, 0xEA;\n\t"
        "lop3.b32 hi, %1, 0x00780000, 0x3F800000, 0xEA;\n\t"
        "mov.b64 v, {lo, hi};\n\t"
        "fma.rn.f32x2 %0, %2, v, %0;\n\t"
        "}"
        : "+l"(acc) : "r"(s), "l"(xp));
}

__device__ __forceinline__ float acc_sum(unsigned long long a, unsigned long long b) {
    float s = __uint_as_float((unsigned)(a & 0xffffffffu)) +
              __uint_as_float((unsigned)(a >> 32));
    s += __uint_as_float((unsigned)(b & 0xffffffffu)) +
         __uint_as_float((unsigned)(b >> 32));
    return s;
}

__global__ __launch_bounds__(TPB, 2)
void qmv_kernel(const float* __restrict__ x, const int* __restrict__ qw,
                const float* __restrict__ scales, const float* __restrict__ zeros,
                const float* __restrict__ bias, float* __restrict__ out) {
    __shared__ ulonglong2 xs2[IN / 4];   // pre-scaled x' pairs, 32 KB
    __shared__ float red[NRG][OPB];      // 8 KB
    __shared__ float r2[4][OPB];
    __shared__ float rs[16], rsp[16];

    const int tid  = threadIdx.x;
    const int lane = tid & 31;
    const int w    = tid >> 5;
    const int og   = lane & 7;                 // output quad 0..7
    const int rg   = (w << 2) | (lane >> 3);   // row-group 0..63

    // ---- stage x' (pairs packed for f32x2), accumulate plain/primed sums ----
    float sp = 0.f, spp = 0.f;
    const float4* xg = reinterpret_cast<const float4*>(x);
    #pragma unroll
    for (int i = tid; i < IN / 4; i += TPB) {
        float4 v = xg[i];
        sp += (v.x + v.y) + (v.z + v.w);
        float px = v.x * 256.f, py = v.y * 16.f, pz = v.z * 256.f, pw = v.w * 16.f;
        spp += (px + py) + (pz + pw);
        unsigned long long lo = ((unsigned long long)__float_as_uint(py) << 32) |
                                __float_as_uint(px);
        unsigned long long hi = ((unsigned long long)__float_as_uint(pw) << 32) |
                                __float_as_uint(pz);
        xs2[i] = make_ulonglong2(lo, hi);
    }
    #pragma unroll
    for (int o = 16; o > 0; o >>= 1) {
        sp  += __shfl_down_sync(0xffffffffu, sp, o);
        spp += __shfl_down_sync(0xffffffffu, spp, o);
    }
    if (lane == 0) { rs[w] = sp; rsp[w] = spp; }
    __syncthreads();

    // ---- main loop: 4 outputs (uint4 load), rows rg + 64*i ----
    const uint4* qp = reinterpret_cast<const uint4*>(qw) +
                      (size_t)rg * (OUT / 4) + blockIdx.x * 8 + og;

    unsigned long long a0A = 0, a0B = 0, a1A = 0, a1B = 0;
    unsigned long long a2A = 0, a2B = 0, a3A = 0, a3B = 0;

    #pragma unroll 4
    for (int i = 0; i < NIT; i++) {
        uint4 wv = qp[(size_t)i * NRG * (OUT / 4)];
        int r = rg + (i << 6);
        ulonglong2 xA = xs2[2 * r];       // pairs (k0,k1), (k2,k3)
        ulonglong2 xB = xs2[2 * r + 1];   // pairs (k4,k5), (k6,k7)

        unsigned s;
        // word 0 -> output o+0
        s = wv.x << 15; dq_fma2(a0A, s, xA.x);
        s = wv.x << 7;  dq_fma2(a0B, s, xA.y);
        s = wv.x >> 1;  dq_fma2(a0A, s, xB.x);
        s = wv.x >> 9;  dq_fma2(a0B, s, xB.y);
        // word 1 -> output o+1
        s = wv.y << 15; dq_fma2(a1A, s, xA.x);
        s = wv.y << 7;  dq_fma2(a1B, s, xA.y);
        s = wv.y >> 1;  dq_fma2(a1A, s, xB.x);
        s = wv.y >> 9;  dq_fma2(a1B, s, xB.y);
        // word 2 -> output o+2
        s = wv.z << 15; dq_fma2(a2A, s, xA.x);
        s = wv.z << 7;  dq_fma2(a2B, s, xA.y);
        s = wv.z >> 1;  dq_fma2(a2A, s, xB.x);
        s = wv.z >> 9;  dq_fma2(a2B, s, xB.y);
        // word 3 -> output o+3
        s = wv.w << 15; dq_fma2(a3A, s, xA.x);
        s = wv.w << 7;  dq_fma2(a3B, s, xA.y);
        s = wv.w >> 1;  dq_fma2(a3A, s, xB.x);
        s = wv.w >> 9;  dq_fma2(a3B, s, xB.y);
    }

    // per-thread totals for its 4 outputs
    {
        float4 f = make_float4(acc_sum(a0A, a0B), acc_sum(a1A, a1B),
                               acc_sum(a2A, a2B), acc_sum(a3A, a3B));
        *reinterpret_cast<float4*>(&red[rg][og * 4]) = f;
    }
    __syncthreads();

    // ---- reduce 64 row-groups per output ----
    if (tid < 128) {
        int o = tid & 31, seg = tid >> 5;
        float s = 0.f;
        #pragma unroll
        for (int j = 0; j < 16; j++) s += red[seg * 16 + j][o];
        r2[seg][o] = s;
    }
    __syncthreads();

    if (tid < OPB) {
        float dot = (r2[0][tid] + r2[1][tid]) + (r2[2][tid] + r2[3][tid]);
        float sx = 0.f, sxp = 0.f;
        #pragma unroll
        for (int i = 0; i < 16; i++) { sx += rs[i]; sxp += rsp[i]; }
        dot -= sxp;   // remove implicit-1.0 bias
        int o = blockIdx.x * OPB + tid;
        out[o] = bias[o] + scales[o] * dot - zeros[o] * sx;
    }
}

extern "C" void kernel_launch(void* const* d_in, const int* in_sizes, int n_in,
                              void* d_out, int out_size) {
    const float* x      = (const float*)d_in[0];
    const int*   qw     = (const int*)d_in[1];
    const float* scales = (const float*)d_in[2];
    const float* zeros  = (const float*)d_in[3];
    const float* bias   = (const float*)d_in[4];
    float* out = (float*)d_out;

    qmv_kernel<<<OUT / OPB, TPB>>>(x, qw, scales, zeros, bias, out);
}